// round 16
// baseline (speedup 1.0000x reference)
#include <cuda_runtime.h>
#include <cuda_bf16.h>
#include <cstdint>

typedef unsigned long long u64;

#define B_   16
#define T_   1024
#define E_   128
#define H_   256
#define G4_  1024
#define NC_  8000
#define NPAD 8064
#define NTILE_N 63
#define NCHUNK  8
#define NTICKETS (NCHUNK * B_ * NTILE_N)   // 8064 fc tiles

// -------- scratch (static device arrays) ----------
__device__ float g_xproj[(size_t)T_ * B_ * G4_];   // [t][b][g]
__device__ int   g_xlong;
__device__ int   g_prog[B_];
__device__ int   g_ppm[128];                       // proj m-tile progress
__device__ __nv_bfloat16 g_Ah[(size_t)B_ * T_ * H_];
__device__ __nv_bfloat16 g_Al[(size_t)B_ * T_ * H_];
__device__ __nv_bfloat16 g_Bh[(size_t)NPAD * H_];
__device__ __nv_bfloat16 g_Bl[(size_t)NPAD * H_];
__device__ __nv_bfloat16 g_Ih[(size_t)T_ * B_ * H_];
__device__ __nv_bfloat16 g_Il[(size_t)T_ * B_ * H_];
__device__ __nv_bfloat16 g_Wh[(size_t)G4_ * H_];
__device__ __nv_bfloat16 g_Wl[(size_t)G4_ * H_];

// -------- packed f32x2 helpers ----------
__device__ __forceinline__ void ffma2(u64 &d, u64 a, u64 b) {
    asm("fma.rn.f32x2 %0, %1, %2, %0;" : "+l"(d) : "l"(a), "l"(b));
}
__device__ __forceinline__ u64 fpack(float x, float y) {
    u64 r; asm("mov.b64 %0, {%1, %2};" : "=l"(r) : "f"(x), "f"(y)); return r;
}
__device__ __forceinline__ float2 funpack(u64 v) {
    float2 r; asm("mov.b64 {%0, %1}, %2;" : "=f"(r.x), "=f"(r.y) : "l"(v)); return r;
}
__device__ __forceinline__ float sigm(float x) { return 1.0f / (1.0f + __expf(-x)); }
__device__ __forceinline__ float tanh_f(float x) { return 2.0f * sigm(2.0f * x) - 1.0f; }

// -------- cluster / mbarrier helpers ----------
__device__ __forceinline__ uint32_t smem_u32(const void *p) {
    return (uint32_t)__cvta_generic_to_shared(p);
}
__device__ __forceinline__ uint32_t mapa_u32(uint32_t a, uint32_t rank) {
    uint32_t r;
    asm("mapa.shared::cluster.u32 %0, %1, %2;" : "=r"(r) : "r"(a), "r"(rank));
    return r;
}
__device__ __forceinline__ void mbar_init(uint32_t mbar, uint32_t cnt) {
    asm volatile("mbarrier.init.shared.b64 [%0], %1;" :: "r"(mbar), "r"(cnt) : "memory");
}
__device__ __forceinline__ void mbar_expect_tx(uint32_t mbar, uint32_t bytes) {
    asm volatile("mbarrier.arrive.expect_tx.shared.b64 _, [%0], %1;" :: "r"(mbar), "r"(bytes) : "memory");
}
__device__ __forceinline__ void mbar_wait(uint32_t mbar, uint32_t parity) {
    asm volatile(
        "{\n\t.reg .pred P;\n\t"
        "WL_%=:\n\t"
        "mbarrier.try_wait.parity.acquire.cta.shared::cta.b64 P, [%0], %1, 0x989680;\n\t"
        "@P bra.uni WD_%=;\n\t"
        "bra.uni WL_%=;\n\t"
        "WD_%=:\n\t}"
        :: "r"(mbar), "r"(parity) : "memory");
}
__device__ __forceinline__ void st_async_u64(uint32_t addr, u64 v, uint32_t mbar) {
    asm volatile("st.async.shared::cluster.mbarrier::complete_tx::bytes.b64 [%0], %1, [%2];"
                 :: "r"(addr), "l"(v), "r"(mbar) : "memory");
}
__device__ __forceinline__ void lds_v2u64(uint32_t a, u64 &x, u64 &y) {
    asm("ld.shared.v2.u64 {%0, %1}, [%2];" : "=l"(x), "=l"(y) : "r"(a));
}
__device__ __forceinline__ int ld_acq(const int *p) {
    int v; asm volatile("ld.acquire.gpu.s32 %0, [%1];" : "=r"(v) : "l"(p) : "memory");
    return v;
}
#define CLUSTER_SYNC() do { \
    asm volatile("barrier.cluster.arrive.aligned;" ::: "memory"); \
    asm volatile("barrier.cluster.wait.aligned;" ::: "memory"); } while (0)

// -------- bf16 mma ----------
__device__ __forceinline__ void mma_bf16(float *d, const uint32_t *a, const uint32_t *b) {
    asm("mma.sync.aligned.m16n8k16.row.col.f32.bf16.bf16.f32 "
        "{%0,%1,%2,%3}, {%4,%5,%6,%7}, {%8,%9}, {%0,%1,%2,%3};"
        : "+f"(d[0]), "+f"(d[1]), "+f"(d[2]), "+f"(d[3])
        : "r"(a[0]), "r"(a[1]), "r"(a[2]), "r"(a[3]), "r"(b[0]), "r"(b[1]));
}

// ===========================================================================
// K0: dtype detect + reset all progress counters (every replay)
// ===========================================================================
__global__ void k_init(const void *xraw) {
    if (threadIdx.x == 0) {
        const unsigned int *xi = (const unsigned int *)xraw;
        int i64 = 1;
        for (int i = 0; i < 64; i++)
            if (xi[2 * i + 1] != 0u) { i64 = 0; break; }
        g_xlong = i64;
    }
    if (threadIdx.x < B_) g_prog[threadIdx.x] = 0;
    if (threadIdx.x < 128) g_ppm[threadIdx.x] = 0;
}

// ===========================================================================
// K_prep: merged gather (blocks 0..1023) + splitW (1024..1087) +
// splitB (1088..1599) — runs all three concurrently.
// ===========================================================================
#define TOT4B ((NPAD * H_) / 4)

__global__ void __launch_bounds__(256) k_prep(
    const void *xraw, const float *embx, const float *embl,
    const float *Wih, const float *fcw)
{
    const int bid = blockIdx.x;
    const int tid = threadIdx.x;

    if (bid < 1024) {
        // ---- gather: embedding -> bf16 hi/lo (m = t*16+b) ----
        const int t = bid;
        __shared__ int xs[B_], ls[B_];
        if (tid < 32) {
            int b = tid >> 1, j = tid & 1;
            long long e = (long long)b * (T_ * 2) + t * 2 + j;
            int v;
            if (g_xlong) v = (int)((const long long *)xraw)[e];
            else         v = ((const int *)xraw)[e];
            if (j == 0) xs[b] = v; else ls[b] = v;
        }
        __syncthreads();
        for (int idx = tid; idx < B_ * 256; idx += 256) {
            int b = idx >> 8, k = idx & 255;
            float v = (k < E_) ? embx[xs[b] * E_ + k] : embl[ls[b] * E_ + (k - E_)];
            __nv_bfloat16 h = __float2bfloat16(v);
            __nv_bfloat16 lo = __float2bfloat16(v - __bfloat162float(h));
            size_t e = ((size_t)t * B_ + b) * 256 + k;
            g_Ih[e] = h;
            g_Il[e] = lo;
        }
    } else if (bid < 1088) {
        // ---- splitW: W_ih -> bf16 hi/lo ----
        for (int idx = (bid - 1024) * 256 + tid; idx < (G4_ * H_) / 4;
             idx += 64 * 256) {
            float4 v = ((const float4 *)Wih)[idx];
            size_t e = (size_t)idx * 4;
            __nv_bfloat162 h01 = __floats2bfloat162_rn(v.x, v.y);
            __nv_bfloat162 h23 = __floats2bfloat162_rn(v.z, v.w);
            __nv_bfloat162 l01 = __floats2bfloat162_rn(v.x - __bfloat162float(h01.x),
                                                       v.y - __bfloat162float(h01.y));
            __nv_bfloat162 l23 = __floats2bfloat162_rn(v.z - __bfloat162float(h23.x),
                                                       v.w - __bfloat162float(h23.y));
            *(__nv_bfloat162 *)(g_Wh + e)     = h01;
            *(__nv_bfloat162 *)(g_Wh + e + 2) = h23;
            *(__nv_bfloat162 *)(g_Wl + e)     = l01;
            *(__nv_bfloat162 *)(g_Wl + e + 2) = l23;
        }
    } else {
        // ---- splitB: fc_w -> bf16 hi/lo (padded) ----
        for (size_t j = (size_t)(bid - 1088) * 256 + tid; j < TOT4B;
             j += (size_t)512 * 256) {
            size_t e = j * 4;
            int n = (int)(e >> 8), k = (int)(e & 255);
            float4 v = make_float4(0.f, 0.f, 0.f, 0.f);
            if (n < NC_) v = *(const float4 *)(fcw + (size_t)n * H_ + k);
            __nv_bfloat162 h01 = __floats2bfloat162_rn(v.x, v.y);
            __nv_bfloat162 h23 = __floats2bfloat162_rn(v.z, v.w);
            __nv_bfloat162 l01 = __floats2bfloat162_rn(v.x - __bfloat162float(h01.x),
                                                       v.y - __bfloat162float(h01.y));
            __nv_bfloat162 l23 = __floats2bfloat162_rn(v.z - __bfloat162float(h23.x),
                                                       v.w - __bfloat162float(h23.y));
            *(__nv_bfloat162 *)(g_Bh + e)     = h01;
            *(__nv_bfloat162 *)(g_Bh + e + 2) = h23;
            *(__nv_bfloat162 *)(g_Bl + e)     = l01;
            *(__nv_bfloat162 *)(g_Bl + e + 2) = l23;
        }
    }
}

// ===========================================================================
// K_proj: input projection GEMM (bf16x3 tensor cores, 3-stage cp.async).
// Publishes per-m-tile progress; triggers dependent launch (k_lstm) at entry.
// ===========================================================================
#define BSTRD 24
#define STAGE_ELEMS (4 * 128 * BSTRD)

__global__ void __launch_bounds__(256) k_proj(const float *bih, const float *bhh)
{
    extern __shared__ __align__(16) __nv_bfloat16 smd[];

    asm volatile("griddepcontrol.launch_dependents;" ::: "memory");

    const int bn = blockIdx.x * 128;
    const int bm = blockIdx.y * 128;

    const int tid = threadIdx.x;
    const int w = tid >> 5, l = tid & 31;
    const int wm = w & 1, wn = w >> 1;
    const int g = l >> 2, tig = l & 3;

    float acc[4][4][4];
#pragma unroll
    for (int i = 0; i < 4; i++)
#pragma unroll
        for (int j = 0; j < 4; j++)
#pragma unroll
            for (int c = 0; c < 4; c++) acc[i][j][c] = 0.0f;

    const __nv_bfloat16 *gsrc0 = g_Ih + (size_t)bm * H_;
    const __nv_bfloat16 *gsrc1 = g_Il + (size_t)bm * H_;
    const __nv_bfloat16 *gsrc2 = g_Wh + (size_t)bn * H_;
    const __nv_bfloat16 *gsrc3 = g_Wl + (size_t)bn * H_;

#define LOAD_CHUNK_P(kc, st) do {                                            \
    int k0 = (kc) * 16;                                                      \
    _Pragma("unroll")                                                        \
    for (int i = 0; i < 4; i++) {                                            \
        int s = i * 256 + tid;                                               \
        int tile = s >> 8;                                                   \
        int rr = (s >> 1) & 127;                                             \
        int cc = s & 1;                                                      \
        const __nv_bfloat16 *src =                                           \
            (tile == 0 ? gsrc0 : tile == 1 ? gsrc1 : tile == 2 ? gsrc2 : gsrc3) \
            + (size_t)rr * H_ + k0 + cc * 8;                                 \
        uint32_t dst = smem_u32(smd + (st) * STAGE_ELEMS                     \
                                + tile * (128 * BSTRD) + rr * BSTRD + cc * 8); \
        asm volatile("cp.async.cg.shared.global [%0], [%1], 16;"             \
                     :: "r"(dst), "l"(src));                                 \
    }                                                                        \
    asm volatile("cp.async.commit_group;");                                  \
} while (0)

    LOAD_CHUNK_P(0, 0);
    LOAD_CHUNK_P(1, 1);
    int st = 0, ld_st = 2;
    for (int kc = 0; kc < 16; kc++) {
        if (kc < 15) asm volatile("cp.async.wait_group 1;");
        else         asm volatile("cp.async.wait_group 0;");
        __syncthreads();
        if (kc + 2 < 16) {
            LOAD_CHUNK_P(kc + 2, ld_st);
            ld_st = (ld_st == 2) ? 0 : ld_st + 1;
        }

        const __nv_bfloat16 *Ah_s = smd + st * STAGE_ELEMS;
        const __nv_bfloat16 *Al_s = Ah_s + 128 * BSTRD;
        const __nv_bfloat16 *Bh_s = Ah_s + 2 * 128 * BSTRD;
        const __nv_bfloat16 *Bl_s = Ah_s + 3 * 128 * BSTRD;

        uint32_t ah[4][4], al[4][4], bh[4][2], bl[4][2];
#pragma unroll
        for (int i = 0; i < 4; i++) {
            int arow = (wm * 64 + i * 16 + g) * BSTRD + 2 * tig;
            ah[i][0] = *(const uint32_t *)(Ah_s + arow);
            ah[i][1] = *(const uint32_t *)(Ah_s + arow + 8 * BSTRD);
            ah[i][2] = *(const uint32_t *)(Ah_s + arow + 8);
            ah[i][3] = *(const uint32_t *)(Ah_s + arow + 8 * BSTRD + 8);
            al[i][0] = *(const uint32_t *)(Al_s + arow);
            al[i][1] = *(const uint32_t *)(Al_s + arow + 8 * BSTRD);
            al[i][2] = *(const uint32_t *)(Al_s + arow + 8);
            al[i][3] = *(const uint32_t *)(Al_s + arow + 8 * BSTRD + 8);
        }
#pragma unroll
        for (int j = 0; j < 4; j++) {
            int brow = (wn * 32 + j * 8 + g) * BSTRD + 2 * tig;
            bh[j][0] = *(const uint32_t *)(Bh_s + brow);
            bh[j][1] = *(const uint32_t *)(Bh_s + brow + 8);
            bl[j][0] = *(const uint32_t *)(Bl_s + brow);
            bl[j][1] = *(const uint32_t *)(Bl_s + brow + 8);
        }
#pragma unroll
        for (int i = 0; i < 4; i++)
#pragma unroll
            for (int j = 0; j < 4; j++) {
                mma_bf16(acc[i][j], ah[i], bh[j]);
                mma_bf16(acc[i][j], al[i], bh[j]);
                mma_bf16(acc[i][j], ah[i], bl[j]);
            }

        st = (st == 2) ? 0 : st + 1;
    }

#pragma unroll
    for (int i = 0; i < 4; i++) {
        int m0 = bm + wm * 64 + i * 16 + g;
#pragma unroll
        for (int j = 0; j < 4; j++) {
            int n0 = bn + wn * 32 + j * 8 + 2 * tig;
            float bx = bih[n0] + bhh[n0];
            float by = bih[n0 + 1] + bhh[n0 + 1];
            *(float2 *)(g_xproj + (size_t)m0 * G4_ + n0) =
                make_float2(acc[i][j][0] + bx, acc[i][j][1] + by);
            *(float2 *)(g_xproj + (size_t)(m0 + 8) * G4_ + n0) =
                make_float2(acc[i][j][2] + bx, acc[i][j][3] + by);
        }
    }

    __syncthreads();
    if (tid == 0) {
        __threadfence();
        atomicAdd(&g_ppm[blockIdx.y], 1);   // m-tile covers t in [by*8, by*8+8)
    }
}

// ===========================================================================
// K2: LSTM recurrence — proven config; PDL-dependent of k_proj (gated by
// g_ppm per 8-step tile); triggers k_fc at t==256 (proj long finished).
// ===========================================================================
__global__ void __launch_bounds__(512, 1) __cluster_dims__(8, 1, 1)
k_lstm(const float *Whh)
{
    const int cta = blockIdx.x;
    const int b   = cta >> 3;
    const int grp = cta & 7;
    const int tid = threadIdx.x;
    const int r = tid >> 2;
    const int q = tid & 3;
    const int gate = r >> 5, lh = r & 31;
    const int row_g = gate * H_ + grp * 32 + lh;

    __shared__ __align__(16) float h_buf[2][272];
    __shared__ float gates_s[128];
    __shared__ __align__(8) u64 mbar[2];

    u64 w2[32];
    {
        const float *wp = Whh + (size_t)row_g * H_ + q * 64;
#pragma unroll
        for (int j = 0; j < 32; j++) w2[j] = *(const u64 *)(wp + 2 * j);
    }

    if (tid < 136) ((float4 *)h_buf)[tid] = make_float4(0.f, 0.f, 0.f, 0.f);

    const uint32_t mbase = smem_u32(&mbar[0]);
    const uint32_t hbase = smem_u32(&h_buf[0][0]);
    if (tid == 0) { mbar_init(mbase, 1); mbar_init(mbase + 8, 1); }
    __syncthreads();
    if (tid == 0) { mbar_expect_tx(mbase, 1024); mbar_expect_tx(mbase + 8, 1024); }

    uint32_t peer_h[8], peer_m[8];
    {
        int k = grp * 32 + 2 * (tid & 15);
        uint32_t off = (uint32_t)(((k >> 6) * 68 + (k & 63)) * 4);
#pragma unroll
        for (int pc = 0; pc < 8; pc++) {
            peer_h[pc] = mapa_u32(hbase, (uint32_t)pc) + off;
            peer_m[pc] = mapa_u32(mbase, (uint32_t)pc);
        }
    }

    float xp = 0.0f;
    if (q == 0) {
        while (ld_acq(&g_ppm[0]) < 8) { }       // proj tile 0 ready
        xp = g_xproj[(size_t)b * G4_ + row_g];
    }
    float creg = 0.0f;
    __syncthreads();
    CLUSTER_SYNC();

    uint32_t ph0 = 0, ph1 = 0;

    for (int t = 0; t < T_; t++) {
        if (t > 0) {
            int p = t & 1;
            uint32_t mb = mbase + (uint32_t)p * 8;
            if (tid < 32) {
                if (p) mbar_wait(mb, ph1);
                else   mbar_wait(mb, ph0);
            }
            if (p) ph1 ^= 1; else ph0 ^= 1;
            asm volatile("bar.sync 0;" ::: "memory");
            if (tid == 0 && t + 2 < T_) mbar_expect_tx(mb, 1024);
        }
        if (t == 256)
            asm volatile("griddepcontrol.launch_dependents;" ::: "memory");

        uint32_t hq = hbase + (uint32_t)(t & 1) * 1088 + (uint32_t)q * 272;
        u64 a0 = 0, a1 = 0, a2 = 0, a3 = 0;
#pragma unroll
        for (int jj = 0; jj < 16; jj += 2) {
            u64 x0, y0, x1, y1;
            lds_v2u64(hq + jj * 16, x0, y0);
            lds_v2u64(hq + jj * 16 + 16, x1, y1);
            ffma2(a0, w2[2 * jj + 0], x0);
            ffma2(a1, w2[2 * jj + 1], y0);
            ffma2(a2, w2[2 * jj + 2], x1);
            ffma2(a3, w2[2 * jj + 3], y1);
        }
        float2 s0 = funpack(a0), s1 = funpack(a1), s2 = funpack(a2), s3 = funpack(a3);
        float sum = ((s0.x + s0.y) + (s1.x + s1.y)) + ((s2.x + s2.y) + (s3.x + s3.y));
        sum += __shfl_xor_sync(0xffffffffu, sum, 1);
        sum += __shfl_xor_sync(0xffffffffu, sum, 2);
        if (q == 0) gates_s[r] = sum + xp;

        float xp_n = 0.0f;
        if (q == 0 && t + 1 < T_) {
            if (((t + 1) & 7) == 0) {
                while (ld_acq(&g_ppm[(t + 1) >> 3]) < 8) { }
            }
            xp_n = g_xproj[(size_t)(t + 1) * (B_ * G4_) + b * G4_ + row_g];
        }

        __syncthreads();

        if (tid < 32) {
            float iv = sigm(gates_s[tid]);
            float fv = sigm(gates_s[32 + tid]);
            float gv = tanh_f(gates_s[64 + tid]);
            float ov = sigm(gates_s[96 + tid]);
            float cn = fv * creg + iv * gv;
            creg = cn;
            float hn = ov * tanh_f(cn);
            __nv_bfloat16 hh = __float2bfloat16(hn);
            __nv_bfloat16 hl = __float2bfloat16(hn - __bfloat162float(hh));
            size_t eo = ((size_t)b * T_ + t) * H_ + grp * 32 + tid;
            g_Ah[eo] = hh;
            g_Al[eo] = hl;
            float he = __shfl_sync(0xffffffffu, hn, 2 * (tid & 15));
            float ho = __shfl_sync(0xffffffffu, hn, 2 * (tid & 15) + 1);
            if (tid < 16 && t < T_ - 1) {
                u64 hv2 = fpack(he, ho);
                uint32_t bo = (uint32_t)((t + 1) & 1) * 1088;
                uint32_t mo = (uint32_t)((t + 1) & 1) * 8;
#pragma unroll
                for (int pc = 0; pc < 8; pc++)
                    st_async_u64(peer_h[pc] + bo, hv2, peer_m[pc] + mo);
            }
            __syncwarp();
            if (tid == 0 && (t & 15) == 15) {
                __threadfence();
                atomicAdd(&g_prog[b], 1);
            }
        }
        xp = xp_n;
    }
    CLUSTER_SYNC();
}

// ===========================================================================
// K3: FC GEMM — bf16x3 3-stage; PDL-dependent of k_lstm, gated on g_prog.
// ===========================================================================
__global__ void __launch_bounds__(256) k_fc(const float *fcb, float *out)
{
    extern __shared__ __align__(16) __nv_bfloat16 smd[];
    __shared__ int ready;

    const int tk = blockIdx.x;
    const int tc = tk / (B_ * NTILE_N);
    const int rr2 = tk - tc * (B_ * NTILE_N);
    const int b  = rr2 / NTILE_N;
    const int ni = rr2 - b * NTILE_N;
    const int bm = b * T_ + tc * 128;
    const int bn = ni * 128;

    const int tid = threadIdx.x;
    if (tid == 0) {
        int need = 64 * (tc + 1);
        while (ld_acq(&g_prog[b]) < need) { }
        ready = 1;
    }
    __syncthreads();

    const int w = tid >> 5, l = tid & 31;
    const int wm = w & 1, wn = w >> 1;
    const int g = l >> 2, tig = l & 3;

    float acc[4][4][4];
#pragma unroll
    for (int i = 0; i < 4; i++)
#pragma unroll
        for (int j = 0; j < 4; j++)
#pragma unroll
            for (int c = 0; c < 4; c++) acc[i][j][c] = 0.0f;

    const __nv_bfloat16 *gsrc0 = g_Ah + (size_t)bm * H_;
    const __nv_bfloat16 *gsrc1 = g_Al + (size_t)bm * H_;
    const __nv_bfloat16 *gsrc2 = g_Bh + (size_t)bn * H_;
    const __nv_bfloat16 *gsrc3 = g_Bl + (size_t)bn * H_;

#define LOAD_CHUNK(kc, st) do {                                              \
    int k0 = (kc) * 16;                                                      \
    _Pragma("unroll")                                                        \
    for (int i = 0; i < 4; i++) {                                            \
        int s = i * 256 + tid;                                               \
        int tile = s >> 8;                                                   \
        int rr = (s >> 1) & 127;                                             \
        int cc = s & 1;                                                      \
        const __nv_bfloat16 *src =                                           \
            (tile == 0 ? gsrc0 : tile == 1 ? gsrc1 : tile == 2 ? gsrc2 : gsrc3) \
            + (size_t)rr * H_ + k0 + cc * 8;                                 \
        uint32_t dst = smem_u32(smd + (st) * STAGE_ELEMS                     \
                                + tile * (128 * BSTRD) + rr * BSTRD + cc * 8); \
        asm volatile("cp.async.cg.shared.global [%0], [%1], 16;"             \
                     :: "r"(dst), "l"(src));                                 \
    }                                                                        \
    asm volatile("cp.async.commit_group;");                                  \
} while (0)

    LOAD_CHUNK(0, 0);
    LOAD_CHUNK(1, 1);
    int st = 0, ld_st = 2;
    for (int kc = 0; kc < 16; kc++) {
        if (kc < 15) asm volatile("cp.async.wait_group 1;");
        else         asm volatile("cp.async.wait_group 0;");
        __syncthreads();
        if (kc + 2 < 16) {
            LOAD_CHUNK(kc + 2, ld_st);
            ld_st = (ld_st == 2) ? 0 : ld_st + 1;
        }

        const __nv_bfloat16 *Ah_s = smd + st * STAGE_ELEMS;
        const __nv_bfloat16 *Al_s = Ah_s + 128 * BSTRD;
        const __nv_bfloat16 *Bh_s = Ah_s + 2 * 128 * BSTRD;
        const __nv_bfloat16 *Bl_s = Ah_s + 3 * 128 * BSTRD;

        uint32_t ah[4][4], al[4][4], bh[4][2], bl[4][2];
#pragma unroll
        for (int i = 0; i < 4; i++) {
            int arow = (wm * 64 + i * 16 + g) * BSTRD + 2 * tig;
            ah[i][0] = *(const uint32_t *)(Ah_s + arow);
            ah[i][1] = *(const uint32_t *)(Ah_s + arow + 8 * BSTRD);
            ah[i][2] = *(const uint32_t *)(Ah_s + arow + 8);
            ah[i][3] = *(const uint32_t *)(Ah_s + arow + 8 * BSTRD + 8);
            al[i][0] = *(const uint32_t *)(Al_s + arow);
            al[i][1] = *(const uint32_t *)(Al_s + arow + 8 * BSTRD);
            al[i][2] = *(const uint32_t *)(Al_s + arow + 8);
            al[i][3] = *(const uint32_t *)(Al_s + arow + 8 * BSTRD + 8);
        }
#pragma unroll
        for (int j = 0; j < 4; j++) {
            int brow = (wn * 32 + j * 8 + g) * BSTRD + 2 * tig;
            bh[j][0] = *(const uint32_t *)(Bh_s + brow);
            bh[j][1] = *(const uint32_t *)(Bh_s + brow + 8);
            bl[j][0] = *(const uint32_t *)(Bl_s + brow);
            bl[j][1] = *(const uint32_t *)(Bl_s + brow + 8);
        }
#pragma unroll
        for (int i = 0; i < 4; i++)
#pragma unroll
            for (int j = 0; j < 4; j++) {
                mma_bf16(acc[i][j], ah[i], bh[j]);
                mma_bf16(acc[i][j], al[i], bh[j]);
                mma_bf16(acc[i][j], ah[i], bl[j]);
            }

        st = (st == 2) ? 0 : st + 1;
    }

#pragma unroll
    for (int i = 0; i < 4; i++) {
        int m0 = bm + wm * 64 + i * 16 + g;
#pragma unroll
        for (int j = 0; j < 4; j++) {
            int n0 = bn + wn * 32 + j * 8 + 2 * tig;
            if (n0 < NC_) {
                float bx = fcb[n0], by = fcb[n0 + 1];
                *(float2 *)(out + (size_t)m0 * NC_ + n0) =
                    make_float2(acc[i][j][0] + bx, acc[i][j][1] + by);
                *(float2 *)(out + (size_t)(m0 + 8) * NC_ + n0) =
                    make_float2(acc[i][j][2] + bx, acc[i][j][3] + by);
            }
        }
    }
    (void)ready;
}

// ===========================================================================
extern "C" void kernel_launch(void *const *d_in, const int *in_sizes, int n_in,
                              void *d_out, int out_size)
{
    (void)in_sizes; (void)n_in; (void)out_size;
    const void  *x    = d_in[0];
    const float *embx = (const float *)d_in[1];
    const float *embl = (const float *)d_in[2];
    const float *Wih  = (const float *)d_in[3];
    const float *Whh  = (const float *)d_in[4];
    const float *bih  = (const float *)d_in[5];
    const float *bhh  = (const float *)d_in[6];
    const float *fcw  = (const float *)d_in[7];
    const float *fcb  = (const float *)d_in[8];
    float *out = (float *)d_out;

    const int fc_smem = 3 * STAGE_ELEMS * (int)sizeof(__nv_bfloat16);  // 73728
    cudaFuncSetAttribute(k_proj, cudaFuncAttributeMaxDynamicSharedMemorySize, fc_smem);
    cudaFuncSetAttribute(k_fc,   cudaFuncAttributeMaxDynamicSharedMemorySize, fc_smem);

    k_init<<<1, 256>>>(x);
    k_prep<<<1600, 256>>>(x, embx, embl, Wih, fcw);
    k_proj<<<dim3(G4_ / 128, (B_ * T_) / 128), 256, fc_smem>>>(bih, bhh);

    // k_lstm: PDL-dependent of k_proj (starts early; gated by g_ppm)
    {
        cudaLaunchConfig_t cfg = {};
        cfg.gridDim = dim3(B_ * 8, 1, 1);
        cfg.blockDim = dim3(512, 1, 1);
        cfg.dynamicSmemBytes = 0;
        cfg.stream = 0;
        cudaLaunchAttribute at[1];
        at[0].id = cudaLaunchAttributeProgrammaticStreamSerialization;
        at[0].val.programmaticStreamSerializationAllowed = 1;
        cfg.attrs = at;
        cfg.numAttrs = 1;
        cudaLaunchKernelEx(&cfg, k_lstm, Whh);
    }

    // k_fc: PDL-dependent of k_lstm (released at t==256; gated by g_prog)
    {
        cudaLaunchConfig_t cfg = {};
        cfg.gridDim = dim3(NTICKETS, 1, 1);
        cfg.blockDim = dim3(256, 1, 1);
        cfg.dynamicSmemBytes = fc_smem;
        cfg.stream = 0;
        cudaLaunchAttribute at[1];
        at[0].id = cudaLaunchAttributeProgrammaticStreamSerialization;
        at[0].val.programmaticStreamSerializationAllowed = 1;
        cfg.attrs = at;
        cfg.numAttrs = 1;
        cudaLaunchKernelEx(&cfg, k_fc, fcb, out);
    }
}

// round 17
// speedup vs baseline: 1.0333x; 1.0333x over previous
#include <cuda_runtime.h>
#include <cuda_bf16.h>
#include <cstdint>

typedef unsigned long long u64;

#define B_   16
#define T_   1024
#define E_   128
#define H_   256
#define G4_  1024
#define NC_  8000
#define NPAD 8064
#define NTILE_N 63
#define NCHUNK  8
#define NTICKETS (NCHUNK * B_ * NTILE_N)   // 8064 fc tiles

// -------- scratch (static device arrays) ----------
__device__ float g_xproj[(size_t)T_ * B_ * G4_];   // [t][b][g]
__device__ int   g_xlong;
__device__ int   g_prog[B_];
__device__ __nv_bfloat16 g_Ah[(size_t)B_ * T_ * H_];
__device__ __nv_bfloat16 g_Al[(size_t)B_ * T_ * H_];
__device__ __nv_bfloat16 g_Bh[(size_t)NPAD * H_];
__device__ __nv_bfloat16 g_Bl[(size_t)NPAD * H_];
__device__ __nv_bfloat16 g_Ih[(size_t)T_ * B_ * H_];
__device__ __nv_bfloat16 g_Il[(size_t)T_ * B_ * H_];
__device__ __nv_bfloat16 g_Wh[(size_t)G4_ * H_];
__device__ __nv_bfloat16 g_Wl[(size_t)G4_ * H_];

// -------- packed f32x2 helpers ----------
__device__ __forceinline__ void ffma2(u64 &d, u64 a, u64 b) {
    asm("fma.rn.f32x2 %0, %1, %2, %0;" : "+l"(d) : "l"(a), "l"(b));
}
__device__ __forceinline__ u64 fpack(float x, float y) {
    u64 r; asm("mov.b64 %0, {%1, %2};" : "=l"(r) : "f"(x), "f"(y)); return r;
}
__device__ __forceinline__ float2 funpack(u64 v) {
    float2 r; asm("mov.b64 {%0, %1}, %2;" : "=f"(r.x), "=f"(r.y) : "l"(v)); return r;
}
__device__ __forceinline__ float sigm(float x) { return 1.0f / (1.0f + __expf(-x)); }
__device__ __forceinline__ float tanh_f(float x) { return 2.0f * sigm(2.0f * x) - 1.0f; }

// -------- cluster / mbarrier helpers ----------
__device__ __forceinline__ uint32_t smem_u32(const void *p) {
    return (uint32_t)__cvta_generic_to_shared(p);
}
__device__ __forceinline__ uint32_t mapa_u32(uint32_t a, uint32_t rank) {
    uint32_t r;
    asm("mapa.shared::cluster.u32 %0, %1, %2;" : "=r"(r) : "r"(a), "r"(rank));
    return r;
}
__device__ __forceinline__ void mbar_init(uint32_t mbar, uint32_t cnt) {
    asm volatile("mbarrier.init.shared.b64 [%0], %1;" :: "r"(mbar), "r"(cnt) : "memory");
}
__device__ __forceinline__ void mbar_expect_tx(uint32_t mbar, uint32_t bytes) {
    asm volatile("mbarrier.arrive.expect_tx.shared.b64 _, [%0], %1;" :: "r"(mbar), "r"(bytes) : "memory");
}
__device__ __forceinline__ void mbar_wait(uint32_t mbar, uint32_t parity) {
    asm volatile(
        "{\n\t.reg .pred P;\n\t"
        "WL_%=:\n\t"
        "mbarrier.try_wait.parity.acquire.cta.shared::cta.b64 P, [%0], %1, 0x989680;\n\t"
        "@P bra.uni WD_%=;\n\t"
        "bra.uni WL_%=;\n\t"
        "WD_%=:\n\t}"
        :: "r"(mbar), "r"(parity) : "memory");
}
__device__ __forceinline__ void st_async_u64(uint32_t addr, u64 v, uint32_t mbar) {
    asm volatile("st.async.shared::cluster.mbarrier::complete_tx::bytes.b64 [%0], %1, [%2];"
                 :: "r"(addr), "l"(v), "r"(mbar) : "memory");
}
__device__ __forceinline__ void lds_v2u64(uint32_t a, u64 &x, u64 &y) {
    asm("ld.shared.v2.u64 {%0, %1}, [%2];" : "=l"(x), "=l"(y) : "r"(a));
}
__device__ __forceinline__ int ld_acq(const int *p) {
    int v; asm volatile("ld.acquire.gpu.s32 %0, [%1];" : "=r"(v) : "l"(p) : "memory");
    return v;
}
#define CLUSTER_SYNC() do { \
    asm volatile("barrier.cluster.arrive.aligned;" ::: "memory"); \
    asm volatile("barrier.cluster.wait.aligned;" ::: "memory"); } while (0)

// -------- bf16 mma ----------
__device__ __forceinline__ void mma_bf16(float *d, const uint32_t *a, const uint32_t *b) {
    asm("mma.sync.aligned.m16n8k16.row.col.f32.bf16.bf16.f32 "
        "{%0,%1,%2,%3}, {%4,%5,%6,%7}, {%8,%9}, {%0,%1,%2,%3};"
        : "+f"(d[0]), "+f"(d[1]), "+f"(d[2]), "+f"(d[3])
        : "r"(a[0]), "r"(a[1]), "r"(a[2]), "r"(a[3]), "r"(b[0]), "r"(b[1]));
}

// ===========================================================================
// K0: dtype detect + reset progress (every replay)
// ===========================================================================
__global__ void k_init(const void *xraw) {
    if (threadIdx.x == 0) {
        const unsigned int *xi = (const unsigned int *)xraw;
        int i64 = 1;
        for (int i = 0; i < 64; i++)
            if (xi[2 * i + 1] != 0u) { i64 = 0; break; }
        g_xlong = i64;
    }
    if (threadIdx.x < B_) g_prog[threadIdx.x] = 0;
}

// ===========================================================================
// K_prep: merged gather (blocks 0..1023) + splitW (1024..1087) +
// splitB (1088..1599)
// ===========================================================================
#define TOT4B ((NPAD * H_) / 4)

__global__ void __launch_bounds__(256) k_prep(
    const void *xraw, const float *embx, const float *embl,
    const float *Wih, const float *fcw)
{
    const int bid = blockIdx.x;
    const int tid = threadIdx.x;

    if (bid < 1024) {
        const int t = bid;
        __shared__ int xs[B_], ls[B_];
        if (tid < 32) {
            int b = tid >> 1, j = tid & 1;
            long long e = (long long)b * (T_ * 2) + t * 2 + j;
            int v;
            if (g_xlong) v = (int)((const long long *)xraw)[e];
            else         v = ((const int *)xraw)[e];
            if (j == 0) xs[b] = v; else ls[b] = v;
        }
        __syncthreads();
        for (int idx = tid; idx < B_ * 256; idx += 256) {
            int b = idx >> 8, k = idx & 255;
            float v = (k < E_) ? embx[xs[b] * E_ + k] : embl[ls[b] * E_ + (k - E_)];
            __nv_bfloat16 h = __float2bfloat16(v);
            __nv_bfloat16 lo = __float2bfloat16(v - __bfloat162float(h));
            size_t e = ((size_t)t * B_ + b) * 256 + k;
            g_Ih[e] = h;
            g_Il[e] = lo;
        }
    } else if (bid < 1088) {
        for (int idx = (bid - 1024) * 256 + tid; idx < (G4_ * H_) / 4;
             idx += 64 * 256) {
            float4 v = ((const float4 *)Wih)[idx];
            size_t e = (size_t)idx * 4;
            __nv_bfloat162 h01 = __floats2bfloat162_rn(v.x, v.y);
            __nv_bfloat162 h23 = __floats2bfloat162_rn(v.z, v.w);
            __nv_bfloat162 l01 = __floats2bfloat162_rn(v.x - __bfloat162float(h01.x),
                                                       v.y - __bfloat162float(h01.y));
            __nv_bfloat162 l23 = __floats2bfloat162_rn(v.z - __bfloat162float(h23.x),
                                                       v.w - __bfloat162float(h23.y));
            *(__nv_bfloat162 *)(g_Wh + e)     = h01;
            *(__nv_bfloat162 *)(g_Wh + e + 2) = h23;
            *(__nv_bfloat162 *)(g_Wl + e)     = l01;
            *(__nv_bfloat162 *)(g_Wl + e + 2) = l23;
        }
    } else {
        for (size_t j = (size_t)(bid - 1088) * 256 + tid; j < TOT4B;
             j += (size_t)512 * 256) {
            size_t e = j * 4;
            int n = (int)(e >> 8), k = (int)(e & 255);
            float4 v = make_float4(0.f, 0.f, 0.f, 0.f);
            if (n < NC_) v = *(const float4 *)(fcw + (size_t)n * H_ + k);
            __nv_bfloat162 h01 = __floats2bfloat162_rn(v.x, v.y);
            __nv_bfloat162 h23 = __floats2bfloat162_rn(v.z, v.w);
            __nv_bfloat162 l01 = __floats2bfloat162_rn(v.x - __bfloat162float(h01.x),
                                                       v.y - __bfloat162float(h01.y));
            __nv_bfloat162 l23 = __floats2bfloat162_rn(v.z - __bfloat162float(h23.x),
                                                       v.w - __bfloat162float(h23.y));
            *(__nv_bfloat162 *)(g_Bh + e)     = h01;
            *(__nv_bfloat162 *)(g_Bh + e + 2) = h23;
            *(__nv_bfloat162 *)(g_Bl + e)     = l01;
            *(__nv_bfloat162 *)(g_Bl + e + 2) = l23;
        }
    }
}

// ===========================================================================
// K_proj: input projection GEMM (bf16x3, 3-stage cp.async) — sequential.
// ===========================================================================
#define BSTRD 24
#define STAGE_ELEMS (4 * 128 * BSTRD)

__global__ void __launch_bounds__(256) k_proj(const float *bih, const float *bhh)
{
    extern __shared__ __align__(16) __nv_bfloat16 smd[];

    const int bn = blockIdx.x * 128;
    const int bm = blockIdx.y * 128;

    const int tid = threadIdx.x;
    const int w = tid >> 5, l = tid & 31;
    const int wm = w & 1, wn = w >> 1;
    const int g = l >> 2, tig = l & 3;

    float acc[4][4][4];
#pragma unroll
    for (int i = 0; i < 4; i++)
#pragma unroll
        for (int j = 0; j < 4; j++)
#pragma unroll
            for (int c = 0; c < 4; c++) acc[i][j][c] = 0.0f;

    const __nv_bfloat16 *gsrc0 = g_Ih + (size_t)bm * H_;
    const __nv_bfloat16 *gsrc1 = g_Il + (size_t)bm * H_;
    const __nv_bfloat16 *gsrc2 = g_Wh + (size_t)bn * H_;
    const __nv_bfloat16 *gsrc3 = g_Wl + (size_t)bn * H_;

#define LOAD_CHUNK_P(kc, st) do {                                            \
    int k0 = (kc) * 16;                                                      \
    _Pragma("unroll")                                                        \
    for (int i = 0; i < 4; i++) {                                            \
        int s = i * 256 + tid;                                               \
        int tile = s >> 8;                                                   \
        int rr = (s >> 1) & 127;                                             \
        int cc = s & 1;                                                      \
        const __nv_bfloat16 *src =                                           \
            (tile == 0 ? gsrc0 : tile == 1 ? gsrc1 : tile == 2 ? gsrc2 : gsrc3) \
            + (size_t)rr * H_ + k0 + cc * 8;                                 \
        uint32_t dst = smem_u32(smd + (st) * STAGE_ELEMS                     \
                                + tile * (128 * BSTRD) + rr * BSTRD + cc * 8); \
        asm volatile("cp.async.cg.shared.global [%0], [%1], 16;"             \
                     :: "r"(dst), "l"(src));                                 \
    }                                                                        \
    asm volatile("cp.async.commit_group;");                                  \
} while (0)

    LOAD_CHUNK_P(0, 0);
    LOAD_CHUNK_P(1, 1);
    int st = 0, ld_st = 2;
    for (int kc = 0; kc < 16; kc++) {
        if (kc < 15) asm volatile("cp.async.wait_group 1;");
        else         asm volatile("cp.async.wait_group 0;");
        __syncthreads();
        if (kc + 2 < 16) {
            LOAD_CHUNK_P(kc + 2, ld_st);
            ld_st = (ld_st == 2) ? 0 : ld_st + 1;
        }

        const __nv_bfloat16 *Ah_s = smd + st * STAGE_ELEMS;
        const __nv_bfloat16 *Al_s = Ah_s + 128 * BSTRD;
        const __nv_bfloat16 *Bh_s = Ah_s + 2 * 128 * BSTRD;
        const __nv_bfloat16 *Bl_s = Ah_s + 3 * 128 * BSTRD;

        uint32_t ah[4][4], al[4][4], bh[4][2], bl[4][2];
#pragma unroll
        for (int i = 0; i < 4; i++) {
            int arow = (wm * 64 + i * 16 + g) * BSTRD + 2 * tig;
            ah[i][0] = *(const uint32_t *)(Ah_s + arow);
            ah[i][1] = *(const uint32_t *)(Ah_s + arow + 8 * BSTRD);
            ah[i][2] = *(const uint32_t *)(Ah_s + arow + 8);
            ah[i][3] = *(const uint32_t *)(Ah_s + arow + 8 * BSTRD + 8);
            al[i][0] = *(const uint32_t *)(Al_s + arow);
            al[i][1] = *(const uint32_t *)(Al_s + arow + 8 * BSTRD);
            al[i][2] = *(const uint32_t *)(Al_s + arow + 8);
            al[i][3] = *(const uint32_t *)(Al_s + arow + 8 * BSTRD + 8);
        }
#pragma unroll
        for (int j = 0; j < 4; j++) {
            int brow = (wn * 32 + j * 8 + g) * BSTRD + 2 * tig;
            bh[j][0] = *(const uint32_t *)(Bh_s + brow);
            bh[j][1] = *(const uint32_t *)(Bh_s + brow + 8);
            bl[j][0] = *(const uint32_t *)(Bl_s + brow);
            bl[j][1] = *(const uint32_t *)(Bl_s + brow + 8);
        }
#pragma unroll
        for (int i = 0; i < 4; i++)
#pragma unroll
            for (int j = 0; j < 4; j++) {
                mma_bf16(acc[i][j], ah[i], bh[j]);
                mma_bf16(acc[i][j], al[i], bh[j]);
                mma_bf16(acc[i][j], ah[i], bl[j]);
            }

        st = (st == 2) ? 0 : st + 1;
    }

#pragma unroll
    for (int i = 0; i < 4; i++) {
        int m0 = bm + wm * 64 + i * 16 + g;
#pragma unroll
        for (int j = 0; j < 4; j++) {
            int n0 = bn + wn * 32 + j * 8 + 2 * tig;
            float bx = bih[n0] + bhh[n0];
            float by = bih[n0 + 1] + bhh[n0 + 1];
            *(float2 *)(g_xproj + (size_t)m0 * G4_ + n0) =
                make_float2(acc[i][j][0] + bx, acc[i][j][1] + by);
            *(float2 *)(g_xproj + (size_t)(m0 + 8) * G4_ + n0) =
                make_float2(acc[i][j][2] + bx, acc[i][j][3] + by);
        }
    }
}

// ===========================================================================
// K2: LSTM recurrence — round-15 exact (proven 2860): direct bf16 h store,
// progress publication, PDL trigger right after cluster handshake.
// ===========================================================================
__global__ void __launch_bounds__(512, 1) __cluster_dims__(8, 1, 1)
k_lstm(const float *Whh)
{
    const int cta = blockIdx.x;
    const int b   = cta >> 3;
    const int grp = cta & 7;
    const int tid = threadIdx.x;
    const int r = tid >> 2;
    const int q = tid & 3;
    const int gate = r >> 5, lh = r & 31;
    const int row_g = gate * H_ + grp * 32 + lh;

    __shared__ __align__(16) float h_buf[2][272];
    __shared__ float gates_s[128];
    __shared__ __align__(8) u64 mbar[2];

    u64 w2[32];
    {
        const float *wp = Whh + (size_t)row_g * H_ + q * 64;
#pragma unroll
        for (int j = 0; j < 32; j++) w2[j] = *(const u64 *)(wp + 2 * j);
    }

    if (tid < 136) ((float4 *)h_buf)[tid] = make_float4(0.f, 0.f, 0.f, 0.f);

    const uint32_t mbase = smem_u32(&mbar[0]);
    const uint32_t hbase = smem_u32(&h_buf[0][0]);
    if (tid == 0) { mbar_init(mbase, 1); mbar_init(mbase + 8, 1); }
    __syncthreads();
    if (tid == 0) { mbar_expect_tx(mbase, 1024); mbar_expect_tx(mbase + 8, 1024); }

    uint32_t peer_h[8], peer_m[8];
    {
        int k = grp * 32 + 2 * (tid & 15);
        uint32_t off = (uint32_t)(((k >> 6) * 68 + (k & 63)) * 4);
#pragma unroll
        for (int pc = 0; pc < 8; pc++) {
            peer_h[pc] = mapa_u32(hbase, (uint32_t)pc) + off;
            peer_m[pc] = mapa_u32(mbase, (uint32_t)pc);
        }
    }

    float xp = (q == 0) ? g_xproj[(size_t)b * G4_ + row_g] : 0.0f;
    float creg = 0.0f;
    __syncthreads();
    CLUSTER_SYNC();

    // all CTAs resident + initialized -> let dependent k_fc start flowing
    asm volatile("griddepcontrol.launch_dependents;" ::: "memory");

    uint32_t ph0 = 0, ph1 = 0;

    for (int t = 0; t < T_; t++) {
        if (t > 0) {
            int p = t & 1;
            uint32_t mb = mbase + (uint32_t)p * 8;
            if (tid < 32) {
                if (p) mbar_wait(mb, ph1);
                else   mbar_wait(mb, ph0);
            }
            if (p) ph1 ^= 1; else ph0 ^= 1;
            asm volatile("bar.sync 0;" ::: "memory");
            if (tid == 0 && t + 2 < T_) mbar_expect_tx(mb, 1024);
        }

        uint32_t hq = hbase + (uint32_t)(t & 1) * 1088 + (uint32_t)q * 272;
        u64 a0 = 0, a1 = 0, a2 = 0, a3 = 0;
#pragma unroll
        for (int jj = 0; jj < 16; jj += 2) {
            u64 x0, y0, x1, y1;
            lds_v2u64(hq + jj * 16, x0, y0);
            lds_v2u64(hq + jj * 16 + 16, x1, y1);
            ffma2(a0, w2[2 * jj + 0], x0);
            ffma2(a1, w2[2 * jj + 1], y0);
            ffma2(a2, w2[2 * jj + 2], x1);
            ffma2(a3, w2[2 * jj + 3], y1);
        }
        float2 s0 = funpack(a0), s1 = funpack(a1), s2 = funpack(a2), s3 = funpack(a3);
        float sum = ((s0.x + s0.y) + (s1.x + s1.y)) + ((s2.x + s2.y) + (s3.x + s3.y));
        sum += __shfl_xor_sync(0xffffffffu, sum, 1);
        sum += __shfl_xor_sync(0xffffffffu, sum, 2);
        if (q == 0) gates_s[r] = sum + xp;

        float xp_n = 0.0f;
        if (q == 0 && t + 1 < T_)
            xp_n = g_xproj[(size_t)(t + 1) * (B_ * G4_) + b * G4_ + row_g];

        __syncthreads();

        if (tid < 32) {
            float iv = sigm(gates_s[tid]);
            float fv = sigm(gates_s[32 + tid]);
            float gv = tanh_f(gates_s[64 + tid]);
            float ov = sigm(gates_s[96 + tid]);
            float cn = fv * creg + iv * gv;
            creg = cn;
            float hn = ov * tanh_f(cn);
            __nv_bfloat16 hh = __float2bfloat16(hn);
            __nv_bfloat16 hl = __float2bfloat16(hn - __bfloat162float(hh));
            size_t eo = ((size_t)b * T_ + t) * H_ + grp * 32 + tid;
            g_Ah[eo] = hh;
            g_Al[eo] = hl;
            float he = __shfl_sync(0xffffffffu, hn, 2 * (tid & 15));
            float ho = __shfl_sync(0xffffffffu, hn, 2 * (tid & 15) + 1);
            if (tid < 16 && t < T_ - 1) {
                u64 hv2 = fpack(he, ho);
                uint32_t bo = (uint32_t)((t + 1) & 1) * 1088;
                uint32_t mo = (uint32_t)((t + 1) & 1) * 8;
#pragma unroll
                for (int pc = 0; pc < 8; pc++)
                    st_async_u64(peer_h[pc] + bo, hv2, peer_m[pc] + mo);
            }
            __syncwarp();
            if (tid == 0 && (t & 15) == 15) {
                __threadfence();
                atomicAdd(&g_prog[b], 1);
            }
        }
        xp = xp_n;
    }
    CLUSTER_SYNC();
}

// ===========================================================================
// K3: FC GEMM — bf16x3, 2-STAGE pipeline (49KB smem) so 2 CTAs/SM fit:
// doubles FC density on idle SMs during the LSTM and in the tail.
// PDL-dependent of k_lstm; tid0 spin-waits per-batch progress.
// ===========================================================================
__global__ void __launch_bounds__(256, 2) k_fc(const float *fcb, float *out)
{
    extern __shared__ __align__(16) __nv_bfloat16 smd[];
    __shared__ int ready;

    const int tk = blockIdx.x;
    const int tc = tk / (B_ * NTILE_N);
    const int rr2 = tk - tc * (B_ * NTILE_N);
    const int b  = rr2 / NTILE_N;
    const int ni = rr2 - b * NTILE_N;
    const int bm = b * T_ + tc * 128;
    const int bn = ni * 128;

    const int tid = threadIdx.x;
    if (tid == 0) {
        int need = 64 * (tc + 1);
        while (ld_acq(&g_prog[b]) < need) { }
        ready = 1;
    }
    __syncthreads();

    const int w = tid >> 5, l = tid & 31;
    const int wm = w & 1, wn = w >> 1;
    const int g = l >> 2, tig = l & 3;

    float acc[4][4][4];
#pragma unroll
    for (int i = 0; i < 4; i++)
#pragma unroll
        for (int j = 0; j < 4; j++)
#pragma unroll
            for (int c = 0; c < 4; c++) acc[i][j][c] = 0.0f;

    const __nv_bfloat16 *gsrc0 = g_Ah + (size_t)bm * H_;
    const __nv_bfloat16 *gsrc1 = g_Al + (size_t)bm * H_;
    const __nv_bfloat16 *gsrc2 = g_Bh + (size_t)bn * H_;
    const __nv_bfloat16 *gsrc3 = g_Bl + (size_t)bn * H_;

#define LOAD_CHUNK(kc, st) do {                                              \
    int k0 = (kc) * 16;                                                      \
    _Pragma("unroll")                                                        \
    for (int i = 0; i < 4; i++) {                                            \
        int s = i * 256 + tid;                                               \
        int tile = s >> 8;                                                   \
        int rr = (s >> 1) & 127;                                             \
        int cc = s & 1;                                                      \
        const __nv_bfloat16 *src =                                           \
            (tile == 0 ? gsrc0 : tile == 1 ? gsrc1 : tile == 2 ? gsrc2 : gsrc3) \
            + (size_t)rr * H_ + k0 + cc * 8;                                 \
        uint32_t dst = smem_u32(smd + (st) * STAGE_ELEMS                     \
                                + tile * (128 * BSTRD) + rr * BSTRD + cc * 8); \
        asm volatile("cp.async.cg.shared.global [%0], [%1], 16;"             \
                     :: "r"(dst), "l"(src));                                 \
    }                                                                        \
    asm volatile("cp.async.commit_group;");                                  \
} while (0)

    LOAD_CHUNK(0, 0);
    int st = 0;
    for (int kc = 0; kc < 16; kc++) {
        if (kc + 1 < 16) {
            LOAD_CHUNK(kc + 1, st ^ 1);
            asm volatile("cp.async.wait_group 1;");
        } else {
            asm volatile("cp.async.wait_group 0;");
        }
        __syncthreads();

        const __nv_bfloat16 *Ah_s = smd + st * STAGE_ELEMS;
        const __nv_bfloat16 *Al_s = Ah_s + 128 * BSTRD;
        const __nv_bfloat16 *Bh_s = Ah_s + 2 * 128 * BSTRD;
        const __nv_bfloat16 *Bl_s = Ah_s + 3 * 128 * BSTRD;

        uint32_t ah[4][4], al[4][4], bh[4][2], bl[4][2];
#pragma unroll
        for (int i = 0; i < 4; i++) {
            int arow = (wm * 64 + i * 16 + g) * BSTRD + 2 * tig;
            ah[i][0] = *(const uint32_t *)(Ah_s + arow);
            ah[i][1] = *(const uint32_t *)(Ah_s + arow + 8 * BSTRD);
            ah[i][2] = *(const uint32_t *)(Ah_s + arow + 8);
            ah[i][3] = *(const uint32_t *)(Ah_s + arow + 8 * BSTRD + 8);
            al[i][0] = *(const uint32_t *)(Al_s + arow);
            al[i][1] = *(const uint32_t *)(Al_s + arow + 8 * BSTRD);
            al[i][2] = *(const uint32_t *)(Al_s + arow + 8);
            al[i][3] = *(const uint32_t *)(Al_s + arow + 8 * BSTRD + 8);
        }
#pragma unroll
        for (int j = 0; j < 4; j++) {
            int brow = (wn * 32 + j * 8 + g) * BSTRD + 2 * tig;
            bh[j][0] = *(const uint32_t *)(Bh_s + brow);
            bh[j][1] = *(const uint32_t *)(Bh_s + brow + 8);
            bl[j][0] = *(const uint32_t *)(Bl_s + brow);
            bl[j][1] = *(const uint32_t *)(Bl_s + brow + 8);
        }
#pragma unroll
        for (int i = 0; i < 4; i++)
#pragma unroll
            for (int j = 0; j < 4; j++) {
                mma_bf16(acc[i][j], ah[i], bh[j]);
                mma_bf16(acc[i][j], al[i], bh[j]);
                mma_bf16(acc[i][j], ah[i], bl[j]);
            }
        __syncthreads();
        st ^= 1;
    }

#pragma unroll
    for (int i = 0; i < 4; i++) {
        int m0 = bm + wm * 64 + i * 16 + g;
#pragma unroll
        for (int j = 0; j < 4; j++) {
            int n0 = bn + wn * 32 + j * 8 + 2 * tig;
            if (n0 < NC_) {
                float bx = fcb[n0], by = fcb[n0 + 1];
                *(float2 *)(out + (size_t)m0 * NC_ + n0) =
                    make_float2(acc[i][j][0] + bx, acc[i][j][1] + by);
                *(float2 *)(out + (size_t)(m0 + 8) * NC_ + n0) =
                    make_float2(acc[i][j][2] + bx, acc[i][j][3] + by);
            }
        }
    }
    (void)ready;
}

// ===========================================================================
extern "C" void kernel_launch(void *const *d_in, const int *in_sizes, int n_in,
                              void *d_out, int out_size)
{
    (void)in_sizes; (void)n_in; (void)out_size;
    const void  *x    = d_in[0];
    const float *embx = (const float *)d_in[1];
    const float *embl = (const float *)d_in[2];
    const float *Wih  = (const float *)d_in[3];
    const float *Whh  = (const float *)d_in[4];
    const float *bih  = (const float *)d_in[5];
    const float *bhh  = (const float *)d_in[6];
    const float *fcw  = (const float *)d_in[7];
    const float *fcb  = (const float *)d_in[8];
    float *out = (float *)d_out;

    const int proj_smem = 3 * STAGE_ELEMS * (int)sizeof(__nv_bfloat16);  // 73728
    const int fc_smem   = 2 * STAGE_ELEMS * (int)sizeof(__nv_bfloat16); // 49152
    cudaFuncSetAttribute(k_proj, cudaFuncAttributeMaxDynamicSharedMemorySize, proj_smem);
    cudaFuncSetAttribute(k_fc,   cudaFuncAttributeMaxDynamicSharedMemorySize, fc_smem);

    k_init<<<1, 256>>>(x);
    k_prep<<<1600, 256>>>(x, embx, embl, Wih, fcw);
    k_proj<<<dim3(G4_ / 128, (B_ * T_) / 128), 256, proj_smem>>>(bih, bhh);
    k_lstm<<<B_ * 8, 512>>>(Whh);

    // k_fc with PDL: starts on idle SMs while k_lstm runs.
    cudaLaunchConfig_t cfg = {};
    cfg.gridDim = dim3(NTICKETS, 1, 1);
    cfg.blockDim = dim3(256, 1, 1);
    cfg.dynamicSmemBytes = fc_smem;
    cfg.stream = 0;
    cudaLaunchAttribute at[1];
    at[0].id = cudaLaunchAttributeProgrammaticStreamSerialization;
    at[0].val.programmaticStreamSerializationAllowed = 1;
    cfg.attrs = at;
    cfg.numAttrs = 1;
    cudaLaunchKernelEx(&cfg, k_fc, fcb, out);
}